// round 11
// baseline (speedup 1.0000x reference)
#include <cuda_runtime.h>
#include <math.h>

#define NN   30000
#define E1   400000
#define C1N  15000
#define E2N  100000
#define C2N  7500
#define NBAT 16
#define NB   592      // 4 blocks/SM on 148 SMs

typedef unsigned long long u64;

// ---------------- scratch (__device__ globals; no dynamic alloc) ----------------
__device__ int      g_cnt_dst1[NN];
__device__ int      g_off1[NN];
__device__ int      g_cur1[NN];
__device__ float4   g_ep1[E1];      // per-edge payload: {src, ea0, ea1, ea2}
__device__ int      g_cnt_c1[C1N];
__device__ int      g_cnt_dst2[C1N];
__device__ int      g_off2[C1N];
__device__ int      g_cur2[C1N];
__device__ float4   g_ep2[E2N];     // per-edge payload: {src, cart0, cart1, cart2}
__device__ float    g_possum[C1N * 3];
__device__ int      g_batchp[C1N];
__device__ unsigned g_xp_u[C1N * 32];
__device__ float    g_W1p[162 * 32];
__device__ unsigned g_absmax;
__device__ float    g_A2[C1N * 864];
__device__ float    g_W2p[864 * 64];
__device__ unsigned g_x3_u[C2N * 64];
__device__ int      g_batch2[C2N];
__device__ float    g_gsum[NBAT * 64];
__device__ int      g_cntb[NBAT];
__device__ unsigned g_alloc1;
__device__ unsigned g_alloc2;
__device__ unsigned g_bcnt = 0;
__device__ unsigned g_bgen = 0;

// ---------------- grid-wide barrier: volatile-load spin (no atomic-ALU pileup) --------------
__device__ __forceinline__ void gsync() {
    __syncthreads();
    if (threadIdx.x == 0) {
        __threadfence();                                     // release my writes
        unsigned gen = *(volatile unsigned*)&g_bgen;         // read BEFORE arrival
        if (atomicAdd(&g_bcnt, 1u) == (unsigned)(gridDim.x - 1)) {
            atomicExch(&g_bcnt, 0u);
            __threadfence();
            atomicExch(&g_bgen, gen + 1u);                   // release all
        } else {
            while (*(volatile unsigned*)&g_bgen == gen) { }  // plain L2 load spin
        }
        __threadfence();                                     // acquire
    }
    __syncthreads();
}

// packed f32x2 helpers (FFMA2 path — PTX-only, doubles fp32 FMA throughput)
__device__ __forceinline__ u64 pk(float lo, float hi) {
    u64 r; asm("mov.b64 %0,{%1,%2};" : "=l"(r) : "f"(lo), "f"(hi)); return r;
}
__device__ __forceinline__ void upk(u64 v, float& lo, float& hi) {
    asm("mov.b64 {%0,%1},%2;" : "=f"(lo), "=f"(hi) : "l"(v));
}
__device__ __forceinline__ u64 fma2(u64 a, u64 b, u64 c) {
    u64 d; asm("fma.rn.f32x2 %0,%1,%2,%3;" : "=l"(d) : "l"(a), "l"(b), "l"(c)); return d;
}

// order-preserving float <-> uint so atomicMax works; 0u == "empty" decodes to 0.0f
__device__ __forceinline__ unsigned fenc(float f) {
    unsigned u = __float_as_uint(f);
    return (u & 0x80000000u) ? ~u : (u | 0x80000000u);
}
__device__ __forceinline__ float fdec(unsigned u) {
    if (u == 0u) return 0.f;
    return (u & 0x80000000u) ? __uint_as_float(u & 0x7FFFFFFFu) : __uint_as_float(~u);
}
__device__ __forceinline__ float elu_f(float x) {
    return x > 0.f ? x : (expf(x) - 1.f);
}

// shared-memory overlay
struct SG2 { u64 A[64][48]; float W[48][64]; };                       // 36864 B
struct SHD { float sg[16 * 64]; float sh[16 * 128]; float sl[160]; }; // 12928 B
struct SP2 { float sp[NBAT * 64]; int sc[NBAT]; };                    //  4160 B
union SMEM { SG2 g2; SHD hd; SP2 p2; };

// =====================================================================================
// ONE persistent kernel: 9 phases separated by grid barriers
// =====================================================================================
__global__ void __launch_bounds__(256, 4) k_all(
    const float* __restrict__ x, const float* __restrict__ ea, const float* __restrict__ pos,
    const int* __restrict__ eidx, const int* __restrict__ batch, const int* __restrict__ cl1,
    const int* __restrict__ eidx2, const int* __restrict__ cl2,
    const float* __restrict__ w1a, const float* __restrict__ b1a,
    const float* __restrict__ w1b, const float* __restrict__ b1b,
    const float* __restrict__ root1, const float* __restrict__ bias1,
    const float* __restrict__ w2a, const float* __restrict__ b2a,
    const float* __restrict__ w2b, const float* __restrict__ b2b,
    const float* __restrict__ root2, const float* __restrict__ bias2,
    const float* __restrict__ fc1w, const float* __restrict__ fc1b,
    const float* __restrict__ fc2w, const float* __restrict__ fc2b,
    float* __restrict__ out)
{
    __shared__ SMEM sm;
    const int tid  = threadIdx.x;
    const int g    = blockIdx.x * 256 + tid;
    const int TS   = NB * 256;               // total threads
    const int gw   = g >> 5;                 // global warp id
    const int GW   = NB * 8;                 // total warps
    const int lane = tid & 31;

    // ---------------- P0: zero scratch + repack fused weights ----------------
    for (int i = g; i < C1N * 32; i += TS) g_xp_u[i] = 0u;
    for (int i = g; i < C2N * 64; i += TS) g_x3_u[i] = 0u;
    for (int i = g; i < C1N * 3;  i += TS) g_possum[i] = 0.f;
    for (int i = g; i < NN;       i += TS) g_cnt_dst1[i] = 0;
    for (int i = g; i < C1N;      i += TS) { g_cnt_c1[i] = 0; g_cnt_dst2[i] = 0; g_batchp[i] = 0; }
    for (int i = g; i < C2N;      i += TS) g_batch2[i] = 0;
    for (int i = g; i < NBAT * 64; i += TS) g_gsum[i] = 0.f;
    for (int i = g; i < NBAT;     i += TS) g_cntb[i] = 0;
    if (g == 0) { g_absmax = 0u; g_alloc1 = 0u; g_alloc2 = 0u; }
    // W1p[j,o]: j=i*26+k (i<6,k<26): k<25 -> w1b[k, i*32+o], k==25 -> b1b[i*32+o];
    //           j in [156,162): root1[j-156, o]
    for (int idx = g; idx < 162 * 32; idx += TS) {
        int j = idx >> 5, o = idx & 31;
        float v;
        if (j < 156) {
            int i = j / 26, k = j % 26;
            v = (k < 25) ? w1b[k * 192 + i * 32 + o] : b1b[i * 32 + o];
        } else {
            v = root1[(j - 156) * 32 + o];
        }
        g_W1p[idx] = v;
    }
    // W2p[j,o]: j=k*32+i (k<26,i<32): k<25 -> w2b[k, i*64+o], k==25 -> b2b[i*64+o];
    //           j in [832,864): root2[j-832, o]
    for (int idx = g; idx < 864 * 64; idx += TS) {
        int j = idx >> 6, o = idx & 63;
        float v;
        if (j < 832) {
            int k = j >> 5, i = j & 31;
            v = (k < 25) ? w2b[k * 2048 + i * 64 + o] : b2b[i * 64 + o];
        } else {
            v = root2[(j - 832) * 64 + o];
        }
        g_W2p[idx] = v;
    }
    gsync();

    // ---------------- P1: degree counts + pos-sum + batchp ----------------
    for (int e = g; e < E1;  e += TS) atomicAdd(&g_cnt_dst1[eidx[E1 + e]], 1);
    for (int e = g; e < E2N; e += TS) atomicAdd(&g_cnt_dst2[eidx2[E2N + e]], 1);
    for (int n = g; n < NN;  n += TS) {
        int c = cl1[n];
        atomicAdd(&g_cnt_c1[c], 1);
        atomicAdd(&g_possum[c * 3 + 0], pos[n * 3 + 0]);
        atomicAdd(&g_possum[c * 3 + 1], pos[n * 3 + 1]);
        atomicAdd(&g_possum[c * 3 + 2], pos[n * 3 + 2]);
        atomicMax(&g_batchp[c], batch[n]);
    }
    gsync();

    // ---------------- P2: segment allocation (scan-free CSR offsets) + pos mean + batch2 ----
    for (int n = g; n < NN; n += TS) {
        int c = g_cnt_dst1[n];
        unsigned o = atomicAdd(&g_alloc1, (unsigned)c);
        g_off1[n] = (int)o; g_cur1[n] = (int)o;
    }
    for (int c = g; c < C1N; c += TS) {
        int cc = g_cnt_dst2[c];
        unsigned o = atomicAdd(&g_alloc2, (unsigned)cc);
        g_off2[c] = (int)o; g_cur2[c] = (int)o;
        float inv = 1.f / (float)max(g_cnt_c1[c], 1);
        g_possum[c * 3 + 0] *= inv;
        g_possum[c * 3 + 1] *= inv;
        g_possum[c * 3 + 2] *= inv;
        atomicMax(&g_batch2[cl2[c]], g_batchp[c]);
    }
    gsync();

    // ---------------- P3: fill CSR edge payloads (+ cartesian + absmax) ----------------
    for (int e = g; e < E1; e += TS) {
        int s = eidx[e], d = eidx[E1 + e];
        int p = atomicAdd(&g_cur1[d], 1);
        g_ep1[p] = make_float4(__int_as_float(s), ea[e * 3 + 0], ea[e * 3 + 1], ea[e * 3 + 2]);
    }
    {
        float m = 0.f;
        for (int e = g; e < E2N; e += TS) {
            int s = eidx2[e], d = eidx2[E2N + e];
            float c0 = g_possum[s * 3 + 0] - g_possum[d * 3 + 0];
            float c1 = g_possum[s * 3 + 1] - g_possum[d * 3 + 1];
            float c2 = g_possum[s * 3 + 2] - g_possum[d * 3 + 2];
            int p = atomicAdd(&g_cur2[d], 1);
            g_ep2[p] = make_float4(__int_as_float(s), c0, c1, c2);
            m = fmaxf(m, fmaxf(fabsf(c0), fmaxf(fabsf(c1), fabsf(c2))));
        }
#pragma unroll
        for (int o = 16; o; o >>= 1) m = fmaxf(m, __shfl_xor_sync(0xffffffffu, m, o));
        if (lane == 0 && m > 0.f) atomicMax(&g_absmax, __float_as_uint(m));
    }
    gsync();

    // ---------------- P4: conv1 + gemm1 + elu + pool1-max (one warp per dst node) ----------
    {
        float wa0 = 0.f, wa1 = 0.f, wa2 = 0.f, ba = 0.f;
        if (lane < 25) { wa0 = w1a[lane]; wa1 = w1a[25 + lane]; wa2 = w1a[50 + lane]; ba = b1a[lane]; }
        float bs1 = bias1[lane];
        for (int n = gw; n < NN; n += GW) {
            u64 acc0 = 0, acc1 = 0, acc2 = 0;
            int off = g_off1[n], deg = g_cnt_dst1[n];
            const float4* ep = &g_ep1[off];
            for (int q = 0; q < deg; q++) {
                float4 p = ep[q];                       // uniform broadcast load
                int s = __float_as_int(p.x);
                float h;
                if (lane < 25) {
                    h = fmaf(p.w, wa2, fmaf(p.z, wa1, fmaf(p.y, wa0, ba)));
                    h = fmaxf(h, 0.f);
                } else {
                    h = (lane == 25) ? 1.f : 0.f;
                }
                u64 hh = pk(h, h);
                const u64* xr = (const u64*)(x + s * 6);  // uniform broadcast, 8B-aligned
                acc0 = fma2(xr[0], hh, acc0);
                acc1 = fma2(xr[1], hh, acc1);
                acc2 = fma2(xr[2], hh, acc2);
            }
            float inv = 1.f / (float)max(deg, 1);
            float sv[6];
            upk(acc0, sv[0], sv[1]); upk(acc1, sv[2], sv[3]); upk(acc2, sv[4], sv[5]);
#pragma unroll
            for (int i = 0; i < 6; i++) sv[i] *= inv;
            float o_acc = bs1;
#pragma unroll
            for (int i = 0; i < 6; i++) {
                float si = sv[i];
#pragma unroll
                for (int k = 0; k < 26; k++) {
                    float av = __shfl_sync(0xffffffffu, si, k);
                    o_acc = fmaf(av, g_W1p[(i * 26 + k) * 32 + lane], o_acc);
                }
            }
            const u64* xs = (const u64*)(x + n * 6);
            float x0, x1, x2, x3, x4, x5;
            upk(xs[0], x0, x1); upk(xs[1], x2, x3); upk(xs[2], x4, x5);
            o_acc = fmaf(x0, g_W1p[156 * 32 + lane], o_acc);
            o_acc = fmaf(x1, g_W1p[157 * 32 + lane], o_acc);
            o_acc = fmaf(x2, g_W1p[158 * 32 + lane], o_acc);
            o_acc = fmaf(x3, g_W1p[159 * 32 + lane], o_acc);
            o_acc = fmaf(x4, g_W1p[160 * 32 + lane], o_acc);
            o_acc = fmaf(x5, g_W1p[161 * 32 + lane], o_acc);
            float v = elu_f(o_acc);
            atomicMax(&g_xp_u[cl1[n] * 32 + lane], fenc(v));
        }
    }
    gsync();

    // ---------------- P5: conv2 (one warp per dst cluster, inline xp decode) ----------------
    {
        float wa0 = 0.f, wa1 = 0.f, wa2 = 0.f, ba = 0.f;
        if (lane < 25) { wa0 = w2a[lane]; wa1 = w2a[25 + lane]; wa2 = w2a[50 + lane]; ba = b2a[lane]; }
        float scale = 0.5f / __uint_as_float(g_absmax);
        for (int c = gw; c < C1N; c += GW) {
            float acc[26];
#pragma unroll
            for (int k = 0; k < 26; k++) acc[k] = 0.f;
            int off = g_off2[c], deg = g_cnt_dst2[c];
            const float4* ep = &g_ep2[off];
            for (int q = 0; q < deg; q++) {
                float4 p = ep[q];
                int s = __float_as_int(p.x);
                float h;
                if (lane < 25) {
                    float c0 = fmaf(p.y, scale, 0.5f);
                    float c1 = fmaf(p.z, scale, 0.5f);
                    float c2 = fmaf(p.w, scale, 0.5f);
                    h = fmaf(c2, wa2, fmaf(c1, wa1, fmaf(c0, wa0, ba)));
                    h = fmaxf(h, 0.f);
                } else {
                    h = (lane == 25) ? 1.f : 0.f;
                }
                float xv = fdec(g_xp_u[s * 32 + lane]);  // coalesced 128B + inline decode
#pragma unroll
                for (int k = 0; k < 26; k++)
                    acc[k] = fmaf(xv, __shfl_sync(0xffffffffu, h, k), acc[k]);
            }
            float inv = 1.f / (float)max(deg, 1);
            float* Arow = &g_A2[c * 864];
#pragma unroll
            for (int k = 0; k < 26; k++) Arow[k * 32 + lane] = acc[k] * inv;
            Arow[832 + lane] = fdec(g_xp_u[c * 32 + lane]);
        }
    }
    gsync();

    // ---------------- P6: GEMM2 [C1,864]@[864,64] smem-tiled FFMA2 + elu + pool2-max -------
    {
        const int warp = tid >> 5;
        float b0 = bias2[2 * lane], b1 = bias2[2 * lane + 1];
        for (int tile = blockIdx.x; tile * 64 < C1N; tile += NB) {
            int row0 = tile * 64;
            u64 acc[8];
#pragma unroll
            for (int r = 0; r < 8; r++) acc[r] = 0;
            for (int kc = 0; kc < 864; kc += 48) {
                for (int i = tid; i < 64 * 48; i += 256) {
                    int r = i / 48, k = i - r * 48;
                    int rr = min(row0 + r, C1N - 1);
                    float v = g_A2[rr * 864 + kc + k];
                    sm.g2.A[r][k] = pk(v, v);
                }
                for (int i = tid; i < 48 * 64; i += 256)
                    sm.g2.W[i >> 6][i & 63] = g_W2p[(kc + (i >> 6)) * 64 + (i & 63)];
                __syncthreads();
                int rb = warp * 8;
#pragma unroll 4
                for (int k = 0; k < 48; k++) {
                    u64 w = *(const u64*)&sm.g2.W[k][2 * lane];
#pragma unroll
                    for (int r = 0; r < 8; r++)
                        acc[r] = fma2(sm.g2.A[rb + r][k], w, acc[r]);
                }
                __syncthreads();
            }
#pragma unroll
            for (int r = 0; r < 8; r++) {
                int n = row0 + warp * 8 + r;
                if (n < C1N) {
                    float a0, a1;
                    upk(acc[r], a0, a1);
                    float v0 = elu_f(a0 + b0);
                    float v1 = elu_f(a1 + b1);
                    int c2 = cl2[n];
                    atomicMax(&g_x3_u[c2 * 64 + 2 * lane + 0], fenc(v0));
                    atomicMax(&g_x3_u[c2 * 64 + 2 * lane + 1], fenc(v1));
                }
            }
        }
    }
    gsync();

    // ---------------- P7: pool2 -> per-batch sums via shared staging ----------------
    {
        for (int i = tid; i < NBAT * 64; i += 256) sm.p2.sp[i] = 0.f;
        if (tid < NBAT) sm.p2.sc[tid] = 0;
        __syncthreads();
        for (int idx = g; idx < C2N * 64; idx += TS) {
            float v = fdec(g_x3_u[idx]);
            int c2 = idx >> 6, o = idx & 63;
            int b = g_batch2[c2];
            atomicAdd(&sm.p2.sp[b * 64 + o], v);
            if (o == 0) atomicAdd(&sm.p2.sc[b], 1);
        }
        __syncthreads();
        for (int i = tid; i < NBAT * 64; i += 256)
            if (sm.p2.sp[i] != 0.f) atomicAdd(&g_gsum[i], sm.p2.sp[i]);
        if (tid < NBAT && sm.p2.sc[tid]) atomicAdd(&g_cntb[tid], sm.p2.sc[tid]);
    }
    gsync();

    // ---------------- P8: head (block 0): mean -> fc1+elu -> fc2 -> log_softmax ------------
    if (blockIdx.x == 0) {
        __syncthreads();
        for (int i = tid; i < 16 * 64; i += 256) {
            int b = i >> 6;
            sm.hd.sg[i] = g_gsum[i] / (float)max(g_cntb[b], 1);
        }
        __syncthreads();
        for (int i = tid; i < 16 * 128; i += 256) {
            int b = i >> 7, j = i & 127;
            float a = fc1b[j];
            for (int q = 0; q < 64; q++) a = fmaf(sm.hd.sg[b * 64 + q], fc1w[q * 128 + j], a);
            sm.hd.sh[i] = elu_f(a);
        }
        __syncthreads();
        for (int i = tid; i < 160; i += 256) {
            int b = i / 10, j = i % 10;
            float a = fc2b[j];
            for (int q = 0; q < 128; q++) a = fmaf(sm.hd.sh[b * 128 + q], fc2w[q * 10 + j], a);
            sm.hd.sl[i] = a;
        }
        __syncthreads();
        if (tid < 16) {
            float m = -1e30f;
            for (int j = 0; j < 10; j++) m = fmaxf(m, sm.hd.sl[tid * 10 + j]);
            float s = 0.f;
            for (int j = 0; j < 10; j++) s += expf(sm.hd.sl[tid * 10 + j] - m);
            float lse = logf(s);
            for (int j = 0; j < 10; j++) out[tid * 10 + j] = sm.hd.sl[tid * 10 + j] - m - lse;
        }
    }
}

// ---------------- host launch: ONE kernel ----------------
extern "C" void kernel_launch(void* const* d_in, const int* in_sizes, int n_in,
                              void* d_out, int out_size) {
    const float *x = 0, *ea = 0, *pos = 0, *w1a = 0, *b1a = 0, *w1b = 0, *b1b = 0,
                *root1 = 0, *bias1 = 0, *w2a = 0, *b2a = 0, *w2b = 0, *b2b = 0,
                *root2 = 0, *bias2 = 0, *fc1w = 0, *fc1b = 0, *fc2w = 0, *fc2b = 0;
    const int *eidx = 0, *batch = 0, *cl1 = 0, *eidx2 = 0, *cl2 = 0;
    int c75 = 0, c25 = 0, c192 = 0, c2048 = 0, c30000 = 0;
    for (int i = 0; i < n_in; i++) {
        const void* p = d_in[i];
        switch (in_sizes[i]) {
            case 180000:  x = (const float*)p; break;
            case 1200000: ea = (const float*)p; break;
            case 90000:   pos = (const float*)p; break;
            case 800000:  eidx = (const int*)p; break;
            case 30000:   if (c30000++ == 0) batch = (const int*)p; else cl1 = (const int*)p; break;
            case 200000:  eidx2 = (const int*)p; break;
            case 15000:   cl2 = (const int*)p; break;
            case 75:      if (c75++ == 0) w1a = (const float*)p; else w2a = (const float*)p; break;
            case 25:      if (c25++ == 0) b1a = (const float*)p; else b2a = (const float*)p; break;
            case 4800:    w1b = (const float*)p; break;
            case 192:     if (c192++ == 0) b1b = (const float*)p; else root1 = (const float*)p; break;
            case 32:      bias1 = (const float*)p; break;
            case 51200:   w2b = (const float*)p; break;
            case 2048:    if (c2048++ == 0) b2b = (const float*)p; else root2 = (const float*)p; break;
            case 64:      bias2 = (const float*)p; break;
            case 8192:    fc1w = (const float*)p; break;
            case 128:     fc1b = (const float*)p; break;
            case 1280:    fc2w = (const float*)p; break;
            case 10:      fc2b = (const float*)p; break;
            default: break;
        }
    }
    float* out = (float*)d_out;
    (void)out_size;

    k_all<<<NB, 256>>>(x, ea, pos, eidx, batch, cl1, eidx2, cl2,
                       w1a, b1a, w1b, b1b, root1, bias1,
                       w2a, b2a, w2b, b2b, root2, bias2,
                       fc1w, fc1b, fc2w, fc2b, out);
}

// round 14
// speedup vs baseline: 1.1599x; 1.1599x over previous
#include <cuda_runtime.h>
#include <math.h>

#define NN   30000
#define E1   400000
#define C1N  15000
#define E2N  100000
#define C2N  7500
#define NBAT 16
#define NB   592      // 4 blocks/SM on 148 SMs

typedef unsigned long long u64;

// ---------------- scratch (__device__ globals; no dynamic alloc) ----------------
__device__ int      g_cnt_dst1[NN];
__device__ int      g_off1[NN];
__device__ int      g_cur1[NN];
__device__ float4   g_ep1[E1];      // per-edge payload: {src, ea0, ea1, ea2}
__device__ int      g_cnt_c1[C1N];
__device__ int      g_cnt_dst2[C1N];
__device__ int      g_off2[C1N];
__device__ int      g_cur2[C1N];
__device__ float4   g_ep2[E2N];     // per-edge payload: {src, cart0, cart1, cart2}
__device__ float    g_possum[C1N * 3];
__device__ int      g_batchp[C1N];
__device__ unsigned g_xp_u[C1N * 32];
__device__ float    g_W1p[162 * 32];
__device__ unsigned g_absmax;
__device__ float    g_A2[C1N * 864];
__device__ float    g_W2p[864 * 64];
__device__ unsigned g_x3_u[C2N * 64];
__device__ int      g_batch2[C2N];
__device__ float    g_gsum[NBAT * 64];
__device__ int      g_cntb[NBAT];
__device__ unsigned g_alloc1;
__device__ unsigned g_alloc2;
__device__ unsigned g_bcnt = 0;
__device__ unsigned g_bgen = 0;

// ---------------- grid-wide barrier: R8 form (empirically best of 3 variants) --------------
__device__ __forceinline__ void gsync() {
    __syncthreads();
    if (threadIdx.x == 0) {
        __threadfence();                                   // release: flush my writes
        unsigned gen = atomicAdd(&g_bgen, 0u);             // L2 read of current generation
        if (atomicAdd(&g_bcnt, 1u) == (unsigned)(gridDim.x - 1)) {
            atomicExch(&g_bcnt, 0u);
            atomicExch(&g_bgen, gen + 1u);                 // release all
        } else {
            while (atomicAdd(&g_bgen, 0u) == gen) { }      // spin via L2
        }
        __threadfence();                                   // acquire: invalidate L1
    }
    __syncthreads();
}

// packed f32x2 helpers (FFMA2 path — PTX-only, doubles fp32 FMA throughput)
__device__ __forceinline__ u64 pk(float lo, float hi) {
    u64 r; asm("mov.b64 %0,{%1,%2};" : "=l"(r) : "f"(lo), "f"(hi)); return r;
}
__device__ __forceinline__ void upk(u64 v, float& lo, float& hi) {
    asm("mov.b64 {%0,%1},%2;" : "=f"(lo), "=f"(hi) : "l"(v));
}
__device__ __forceinline__ u64 fma2(u64 a, u64 b, u64 c) {
    u64 d; asm("fma.rn.f32x2 %0,%1,%2,%3;" : "=l"(d) : "l"(a), "l"(b), "l"(c)); return d;
}

// order-preserving float <-> uint so atomicMax works; 0u == "empty" decodes to 0.0f
__device__ __forceinline__ unsigned fenc(float f) {
    unsigned u = __float_as_uint(f);
    return (u & 0x80000000u) ? ~u : (u | 0x80000000u);
}
__device__ __forceinline__ float fdec(unsigned u) {
    if (u == 0u) return 0.f;
    return (u & 0x80000000u) ? __uint_as_float(u & 0x7FFFFFFFu) : __uint_as_float(~u);
}
__device__ __forceinline__ float elu_f(float x) {
    return x > 0.f ? x : (expf(x) - 1.f);
}

// shared-memory overlay
struct SG2 { u64 A[64][48]; float W[48][64]; };                       // 36864 B
struct SHD { float sg[16 * 64]; float sh[16 * 128]; float sl[160]; }; // 12928 B
struct SP2 { float sp[NBAT * 64]; int sc[NBAT]; };                    //  4160 B
union SMEM { SG2 g2; SHD hd; SP2 p2; };

// =====================================================================================
// ONE persistent kernel: 9 phases separated by grid barriers
// =====================================================================================
__global__ void __launch_bounds__(256, 4) k_all(
    const float* __restrict__ x, const float* __restrict__ ea, const float* __restrict__ pos,
    const int* __restrict__ eidx, const int* __restrict__ batch, const int* __restrict__ cl1,
    const int* __restrict__ eidx2, const int* __restrict__ cl2,
    const float* __restrict__ w1a, const float* __restrict__ b1a,
    const float* __restrict__ w1b, const float* __restrict__ b1b,
    const float* __restrict__ root1, const float* __restrict__ bias1,
    const float* __restrict__ w2a, const float* __restrict__ b2a,
    const float* __restrict__ w2b, const float* __restrict__ b2b,
    const float* __restrict__ root2, const float* __restrict__ bias2,
    const float* __restrict__ fc1w, const float* __restrict__ fc1b,
    const float* __restrict__ fc2w, const float* __restrict__ fc2b,
    float* __restrict__ out)
{
    __shared__ SMEM sm;
    const int tid  = threadIdx.x;
    const int g    = blockIdx.x * 256 + tid;
    const int TS   = NB * 256;               // total threads
    const int gw   = g >> 5;                 // global warp id
    const int GW   = NB * 8;                 // total warps
    const int lane = tid & 31;

    // ---------------- P0: zero scratch + repack fused weights ----------------
    for (int i = g; i < C1N * 32; i += TS) g_xp_u[i] = 0u;
    for (int i = g; i < C2N * 64; i += TS) g_x3_u[i] = 0u;
    for (int i = g; i < C1N * 3;  i += TS) g_possum[i] = 0.f;
    for (int i = g; i < NN;       i += TS) g_cnt_dst1[i] = 0;
    for (int i = g; i < C1N;      i += TS) { g_cnt_c1[i] = 0; g_cnt_dst2[i] = 0; g_batchp[i] = 0; }
    for (int i = g; i < C2N;      i += TS) g_batch2[i] = 0;
    for (int i = g; i < NBAT * 64; i += TS) g_gsum[i] = 0.f;
    for (int i = g; i < NBAT;     i += TS) g_cntb[i] = 0;
    if (g == 0) { g_absmax = 0u; g_alloc1 = 0u; g_alloc2 = 0u; }
    // W1p[j,o]: j=i*26+k (i<6,k<26): k<25 -> w1b[k, i*32+o], k==25 -> b1b[i*32+o];
    //           j in [156,162): root1[j-156, o]
    for (int idx = g; idx < 162 * 32; idx += TS) {
        int j = idx >> 5, o = idx & 31;
        float v;
        if (j < 156) {
            int i = j / 26, k = j % 26;
            v = (k < 25) ? w1b[k * 192 + i * 32 + o] : b1b[i * 32 + o];
        } else {
            v = root1[(j - 156) * 32 + o];
        }
        g_W1p[idx] = v;
    }
    // W2p[j,o]: j=k*32+i (k<26,i<32): k<25 -> w2b[k, i*64+o], k==25 -> b2b[i*64+o];
    //           j in [832,864): root2[j-832, o]
    for (int idx = g; idx < 864 * 64; idx += TS) {
        int j = idx >> 6, o = idx & 63;
        float v;
        if (j < 832) {
            int k = j >> 5, i = j & 31;
            v = (k < 25) ? w2b[k * 2048 + i * 64 + o] : b2b[i * 64 + o];
        } else {
            v = root2[(j - 832) * 64 + o];
        }
        g_W2p[idx] = v;
    }
    gsync();

    // ---------------- P1: degree counts + pos-sum + batchp ----------------
    for (int e = g; e < E1;  e += TS) atomicAdd(&g_cnt_dst1[eidx[E1 + e]], 1);
    for (int e = g; e < E2N; e += TS) atomicAdd(&g_cnt_dst2[eidx2[E2N + e]], 1);
    for (int n = g; n < NN;  n += TS) {
        int c = cl1[n];
        atomicAdd(&g_cnt_c1[c], 1);
        atomicAdd(&g_possum[c * 3 + 0], pos[n * 3 + 0]);
        atomicAdd(&g_possum[c * 3 + 1], pos[n * 3 + 1]);
        atomicAdd(&g_possum[c * 3 + 2], pos[n * 3 + 2]);
        atomicMax(&g_batchp[c], batch[n]);
    }
    gsync();

    // ---------------- P2: segment allocation (scan-free CSR offsets) + pos mean + batch2 ----
    for (int n = g; n < NN; n += TS) {
        int c = g_cnt_dst1[n];
        unsigned o = atomicAdd(&g_alloc1, (unsigned)c);
        g_off1[n] = (int)o; g_cur1[n] = (int)o;
    }
    for (int c = g; c < C1N; c += TS) {
        int cc = g_cnt_dst2[c];
        unsigned o = atomicAdd(&g_alloc2, (unsigned)cc);
        g_off2[c] = (int)o; g_cur2[c] = (int)o;
        float inv = 1.f / (float)max(g_cnt_c1[c], 1);
        g_possum[c * 3 + 0] *= inv;
        g_possum[c * 3 + 1] *= inv;
        g_possum[c * 3 + 2] *= inv;
        atomicMax(&g_batch2[cl2[c]], g_batchp[c]);
    }
    gsync();

    // ---------------- P3: fill CSR edge payloads (+ cartesian + absmax) ----------------
    for (int e = g; e < E1; e += TS) {
        int s = eidx[e], d = eidx[E1 + e];
        int p = atomicAdd(&g_cur1[d], 1);
        g_ep1[p] = make_float4(__int_as_float(s), ea[e * 3 + 0], ea[e * 3 + 1], ea[e * 3 + 2]);
    }
    {
        float m = 0.f;
        for (int e = g; e < E2N; e += TS) {
            int s = eidx2[e], d = eidx2[E2N + e];
            float c0 = g_possum[s * 3 + 0] - g_possum[d * 3 + 0];
            float c1 = g_possum[s * 3 + 1] - g_possum[d * 3 + 1];
            float c2 = g_possum[s * 3 + 2] - g_possum[d * 3 + 2];
            int p = atomicAdd(&g_cur2[d], 1);
            g_ep2[p] = make_float4(__int_as_float(s), c0, c1, c2);
            m = fmaxf(m, fmaxf(fabsf(c0), fmaxf(fabsf(c1), fabsf(c2))));
        }
#pragma unroll
        for (int o = 16; o; o >>= 1) m = fmaxf(m, __shfl_xor_sync(0xffffffffu, m, o));
        if (lane == 0 && m > 0.f) atomicMax(&g_absmax, __float_as_uint(m));
    }
    gsync();

    // ---------------- P4: conv1 + gemm1 + elu + pool1-max (warp/node, 1-deep prefetch) -----
    {
        float wa0 = 0.f, wa1 = 0.f, wa2 = 0.f, ba = 0.f;
        if (lane < 25) { wa0 = w1a[lane]; wa1 = w1a[25 + lane]; wa2 = w1a[50 + lane]; ba = b1a[lane]; }
        float bs1 = bias1[lane];
        for (int n = gw; n < NN; n += GW) {
            u64 acc0 = 0, acc1 = 0, acc2 = 0;
            int off = g_off1[n], deg = g_cnt_dst1[n];
            const float4* ep = &g_ep1[off];
            float4 p = make_float4(0, 0, 0, 0);
            if (deg > 0) p = ep[0];
            for (int q = 0; q < deg; q++) {
                float4 pn = p;
                if (q + 1 < deg) pn = ep[q + 1];        // prefetch next payload (independent)
                int s = __float_as_int(p.x);
                float h;
                if (lane < 25) {
                    h = fmaf(p.w, wa2, fmaf(p.z, wa1, fmaf(p.y, wa0, ba)));
                    h = fmaxf(h, 0.f);
                } else {
                    h = (lane == 25) ? 1.f : 0.f;
                }
                u64 hh = pk(h, h);
                const u64* xr = (const u64*)(x + s * 6);  // uniform broadcast, 8B-aligned
                acc0 = fma2(xr[0], hh, acc0);
                acc1 = fma2(xr[1], hh, acc1);
                acc2 = fma2(xr[2], hh, acc2);
                p = pn;
            }
            float inv = 1.f / (float)max(deg, 1);
            float sv[6];
            upk(acc0, sv[0], sv[1]); upk(acc1, sv[2], sv[3]); upk(acc2, sv[4], sv[5]);
#pragma unroll
            for (int i = 0; i < 6; i++) sv[i] *= inv;
            float o_acc = bs1;
#pragma unroll
            for (int i = 0; i < 6; i++) {
                float si = sv[i];
#pragma unroll
                for (int k = 0; k < 26; k++) {
                    float av = __shfl_sync(0xffffffffu, si, k);
                    o_acc = fmaf(av, g_W1p[(i * 26 + k) * 32 + lane], o_acc);
                }
            }
            const u64* xs = (const u64*)(x + n * 6);
            float x0, x1, x2, x3, x4, x5;
            upk(xs[0], x0, x1); upk(xs[1], x2, x3); upk(xs[2], x4, x5);
            o_acc = fmaf(x0, g_W1p[156 * 32 + lane], o_acc);
            o_acc = fmaf(x1, g_W1p[157 * 32 + lane], o_acc);
            o_acc = fmaf(x2, g_W1p[158 * 32 + lane], o_acc);
            o_acc = fmaf(x3, g_W1p[159 * 32 + lane], o_acc);
            o_acc = fmaf(x4, g_W1p[160 * 32 + lane], o_acc);
            o_acc = fmaf(x5, g_W1p[161 * 32 + lane], o_acc);
            float v = elu_f(o_acc);
            atomicMax(&g_xp_u[cl1[n] * 32 + lane], fenc(v));
        }
    }
    gsync();

    // ---------------- P5: conv2 (warp/cluster, inline xp decode, 1-deep prefetch) ----------
    {
        float wa0 = 0.f, wa1 = 0.f, wa2 = 0.f, ba = 0.f;
        if (lane < 25) { wa0 = w2a[lane]; wa1 = w2a[25 + lane]; wa2 = w2a[50 + lane]; ba = b2a[lane]; }
        float scale = 0.5f / __uint_as_float(g_absmax);
        for (int c = gw; c < C1N; c += GW) {
            float acc[26];
#pragma unroll
            for (int k = 0; k < 26; k++) acc[k] = 0.f;
            int off = g_off2[c], deg = g_cnt_dst2[c];
            const float4* ep = &g_ep2[off];
            float4 p = make_float4(0, 0, 0, 0);
            if (deg > 0) p = ep[0];
            for (int q = 0; q < deg; q++) {
                float4 pn = p;
                if (q + 1 < deg) pn = ep[q + 1];        // prefetch next payload (independent)
                int s = __float_as_int(p.x);
                float h;
                if (lane < 25) {
                    float c0 = fmaf(p.y, scale, 0.5f);
                    float c1 = fmaf(p.z, scale, 0.5f);
                    float c2 = fmaf(p.w, scale, 0.5f);
                    h = fmaf(c2, wa2, fmaf(c1, wa1, fmaf(c0, wa0, ba)));
                    h = fmaxf(h, 0.f);
                } else {
                    h = (lane == 25) ? 1.f : 0.f;
                }
                float xv = fdec(g_xp_u[s * 32 + lane]);  // coalesced 128B + inline decode
#pragma unroll
                for (int k = 0; k < 26; k++)
                    acc[k] = fmaf(xv, __shfl_sync(0xffffffffu, h, k), acc[k]);
                p = pn;
            }
            float inv = 1.f / (float)max(deg, 1);
            float* Arow = &g_A2[c * 864];
#pragma unroll
            for (int k = 0; k < 26; k++) Arow[k * 32 + lane] = acc[k] * inv;
            Arow[832 + lane] = fdec(g_xp_u[c * 32 + lane]);
        }
    }
    gsync();

    // ---------------- P6: GEMM2 [C1,864]@[864,64] smem-tiled FFMA2 + elu + pool2-max -------
    {
        const int warp = tid >> 5;
        float b0 = bias2[2 * lane], b1 = bias2[2 * lane + 1];
        for (int tile = blockIdx.x; tile * 64 < C1N; tile += NB) {
            int row0 = tile * 64;
            u64 acc[8];
#pragma unroll
            for (int r = 0; r < 8; r++) acc[r] = 0;
            for (int kc = 0; kc < 864; kc += 48) {
                for (int i = tid; i < 64 * 48; i += 256) {
                    int r = i / 48, k = i - r * 48;
                    int rr = min(row0 + r, C1N - 1);
                    float v = g_A2[rr * 864 + kc + k];
                    sm.g2.A[r][k] = pk(v, v);
                }
                for (int i = tid; i < 48 * 64; i += 256)
                    sm.g2.W[i >> 6][i & 63] = g_W2p[(kc + (i >> 6)) * 64 + (i & 63)];
                __syncthreads();
                int rb = warp * 8;
#pragma unroll 4
                for (int k = 0; k < 48; k++) {
                    u64 w = *(const u64*)&sm.g2.W[k][2 * lane];
#pragma unroll
                    for (int r = 0; r < 8; r++)
                        acc[r] = fma2(sm.g2.A[rb + r][k], w, acc[r]);
                }
                __syncthreads();
            }
#pragma unroll
            for (int r = 0; r < 8; r++) {
                int n = row0 + warp * 8 + r;
                if (n < C1N) {
                    float a0, a1;
                    upk(acc[r], a0, a1);
                    float v0 = elu_f(a0 + b0);
                    float v1 = elu_f(a1 + b1);
                    int c2 = cl2[n];
                    atomicMax(&g_x3_u[c2 * 64 + 2 * lane + 0], fenc(v0));
                    atomicMax(&g_x3_u[c2 * 64 + 2 * lane + 1], fenc(v1));
                }
            }
        }
    }
    gsync();

    // ---------------- P7: pool2 -> per-batch sums via shared staging ----------------
    {
        for (int i = tid; i < NBAT * 64; i += 256) sm.p2.sp[i] = 0.f;
        if (tid < NBAT) sm.p2.sc[tid] = 0;
        __syncthreads();
        for (int idx = g; idx < C2N * 64; idx += TS) {
            float v = fdec(g_x3_u[idx]);
            int c2 = idx >> 6, o = idx & 63;
            int b = g_batch2[c2];
            atomicAdd(&sm.p2.sp[b * 64 + o], v);
            if (o == 0) atomicAdd(&sm.p2.sc[b], 1);
        }
        __syncthreads();
        for (int i = tid; i < NBAT * 64; i += 256)
            if (sm.p2.sp[i] != 0.f) atomicAdd(&g_gsum[i], sm.p2.sp[i]);
        if (tid < NBAT && sm.p2.sc[tid]) atomicAdd(&g_cntb[tid], sm.p2.sc[tid]);
    }
    gsync();

    // ---------------- P8: head (block 0): mean -> fc1+elu -> fc2 -> log_softmax ------------
    if (blockIdx.x == 0) {
        __syncthreads();
        for (int i = tid; i < 16 * 64; i += 256) {
            int b = i >> 6;
            sm.hd.sg[i] = g_gsum[i] / (float)max(g_cntb[b], 1);
        }
        __syncthreads();
        for (int i = tid; i < 16 * 128; i += 256) {
            int b = i >> 7, j = i & 127;
            float a = fc1b[j];
            for (int q = 0; q < 64; q++) a = fmaf(sm.hd.sg[b * 64 + q], fc1w[q * 128 + j], a);
            sm.hd.sh[i] = elu_f(a);
        }
        __syncthreads();
        for (int i = tid; i < 160; i += 256) {
            int b = i / 10, j = i % 10;
            float a = fc2b[j];
            for (int q = 0; q < 128; q++) a = fmaf(sm.hd.sh[b * 128 + q], fc2w[q * 10 + j], a);
            sm.hd.sl[i] = a;
        }
        __syncthreads();
        if (tid < 16) {
            float m = -1e30f;
            for (int j = 0; j < 10; j++) m = fmaxf(m, sm.hd.sl[tid * 10 + j]);
            float s = 0.f;
            for (int j = 0; j < 10; j++) s += expf(sm.hd.sl[tid * 10 + j] - m);
            float lse = logf(s);
            for (int j = 0; j < 10; j++) out[tid * 10 + j] = sm.hd.sl[tid * 10 + j] - m - lse;
        }
    }
}

// ---------------- host launch: ONE kernel ----------------
extern "C" void kernel_launch(void* const* d_in, const int* in_sizes, int n_in,
                              void* d_out, int out_size) {
    const float *x = 0, *ea = 0, *pos = 0, *w1a = 0, *b1a = 0, *w1b = 0, *b1b = 0,
                *root1 = 0, *bias1 = 0, *w2a = 0, *b2a = 0, *w2b = 0, *b2b = 0,
                *root2 = 0, *bias2 = 0, *fc1w = 0, *fc1b = 0, *fc2w = 0, *fc2b = 0;
    const int *eidx = 0, *batch = 0, *cl1 = 0, *eidx2 = 0, *cl2 = 0;
    int c75 = 0, c25 = 0, c192 = 0, c2048 = 0, c30000 = 0;
    for (int i = 0; i < n_in; i++) {
        const void* p = d_in[i];
        switch (in_sizes[i]) {
            case 180000:  x = (const float*)p; break;
            case 1200000: ea = (const float*)p; break;
            case 90000:   pos = (const float*)p; break;
            case 800000:  eidx = (const int*)p; break;
            case 30000:   if (c30000++ == 0) batch = (const int*)p; else cl1 = (const int*)p; break;
            case 200000:  eidx2 = (const int*)p; break;
            case 15000:   cl2 = (const int*)p; break;
            case 75:      if (c75++ == 0) w1a = (const float*)p; else w2a = (const float*)p; break;
            case 25:      if (c25++ == 0) b1a = (const float*)p; else b2a = (const float*)p; break;
            case 4800:    w1b = (const float*)p; break;
            case 192:     if (c192++ == 0) b1b = (const float*)p; else root1 = (const float*)p; break;
            case 32:      bias1 = (const float*)p; break;
            case 51200:   w2b = (const float*)p; break;
            case 2048:    if (c2048++ == 0) b2b = (const float*)p; else root2 = (const float*)p; break;
            case 64:      bias2 = (const float*)p; break;
            case 8192:    fc1w = (const float*)p; break;
            case 128:     fc1b = (const float*)p; break;
            case 1280:    fc2w = (const float*)p; break;
            case 10:      fc2b = (const float*)p; break;
            default: break;
        }
    }
    float* out = (float*)d_out;
    (void)out_size;

    k_all<<<NB, 256>>>(x, ea, pos, eidx, batch, cl1, eidx2, cl2,
                       w1a, b1a, w1b, b1b, root1, bias1,
                       w2a, b2a, w2b, b2b, root2, bias2,
                       fc1w, fc1b, fc2w, fc2b, out);
}